// round 14
// baseline (speedup 1.0000x reference)
#include <cuda_runtime.h>
#include <cuda_fp16.h>
#include <cstdint>

// Problem constants
#define BB 8
#define TT 2048
#define CC 1024
#define HH 64

// k projection scratch: fp16, NATURAL layout
__device__ __half g_kbuf[BB * TT * HH];
// KV-split partials (split-0) + per-row (m,l) + pair flags (self-resetting)
__device__ float g_part[128 * 64 * 64];
__device__ float g_stats[128 * 64 * 2];
__device__ int g_pflags[128];
// proj tile flags: one per 64-row tile of kbuf (256 tiles); zeroed each replay
__device__ int g_tflags[256];

// item order sorted by iteration count (descending), 48 items per batch
__constant__ int c_order[48] = {
    46,47,25,27,28,29,30,31,                 // 8 iters
    44,45,17,19,20,21,22,23,24,26,           // 7
    42,43, 9,11,12,13,14,15,16,18,           // 6
    40,41, 1, 3, 4, 5, 6, 7, 8,10,           // 5
    38,39, 0, 2,                             // 4
    36,37, 34,35, 32,33                      // 3,2,1
};

// ---------------------------------------------------------------------------
// helpers
// ---------------------------------------------------------------------------
__device__ __forceinline__ void mma16(float* c, const uint32_t* a,
                                      uint32_t b0, uint32_t b1) {
    asm volatile(
        "mma.sync.aligned.m16n8k16.row.col.f32.f16.f16.f32 "
        "{%0,%1,%2,%3}, {%4,%5,%6,%7}, {%8,%9}, {%0,%1,%2,%3};"
        : "+f"(c[0]), "+f"(c[1]), "+f"(c[2]), "+f"(c[3])
        : "r"(a[0]), "r"(a[1]), "r"(a[2]), "r"(a[3]), "r"(b0), "r"(b1));
}

__device__ __forceinline__ void ldsm4(uint32_t& r0, uint32_t& r1, uint32_t& r2,
                                      uint32_t& r3, uint32_t addr) {
    asm volatile("ldmatrix.sync.aligned.m8n8.x4.shared.b16 {%0,%1,%2,%3}, [%4];"
                 : "=r"(r0), "=r"(r1), "=r"(r2), "=r"(r3) : "r"(addr));
}

__device__ __forceinline__ void ldsm4t(uint32_t& r0, uint32_t& r1, uint32_t& r2,
                                       uint32_t& r3, uint32_t addr) {
    asm volatile("ldmatrix.sync.aligned.m8n8.x4.trans.shared.b16 {%0,%1,%2,%3}, [%4];"
                 : "=r"(r0), "=r"(r1), "=r"(r2), "=r"(r3) : "r"(addr));
}

__device__ __forceinline__ uint32_t packh2(float lo, float hi) {
    uint32_t d;
    asm("cvt.rn.f16x2.f32 %0, %1, %2;" : "=r"(d) : "f"(hi), "f"(lo));
    return d;
}

__device__ __forceinline__ float ex2f(float x) {
    float y;
    asm("ex2.approx.ftz.f32 %0, %1;" : "=f"(y) : "f"(x));
    return y;
}

__device__ __forceinline__ uint32_t h2ex2(uint32_t x) {
    uint32_t y;
    asm("ex2.approx.f16x2 %0, %1;" : "=r"(y) : "r"(x));
    return y;
}

__device__ __forceinline__ void cpa16(uint32_t dst, const void* src) {
    asm volatile("cp.async.cg.shared.global [%0], [%1], 16;" :: "r"(dst), "l"(src));
}
__device__ __forceinline__ void cpa_commit() {
    asm volatile("cp.async.commit_group;");
}

// ---------------------------------------------------------------------------
// reset kernel: zero the 256 tile flags (pair flags self-reset)
// ---------------------------------------------------------------------------
__global__ void reset_kernel(int* __restrict__ tflags) {
    tflags[threadIdx.x] = 0;
}

// ---------------------------------------------------------------------------
// Fused kernel: [proj phase for ranks 128..383] -> causal flash attention.
// 384 blocks x 128 threads, 3 CTAs/SM => ALL blocks co-resident (spin-safe).
// ---------------------------------------------------------------------------
#define QT 64
#define KT 128
#define QS2 72
#define KS2 72
#define KSTG (KT * KS2)
#define C1 0.0450842200277801f   // log2(e) / 32
#define ONESH2 0x3C003C00u

#define FUSED_SMEM_BYTES ((QT * QS2 + 2 * KT * KS2) * 2)   // 46080

// proj-phase smem layout (fits inside FUSED_SMEM_BYTES):
#define PJXS 36                                 // x stage stride (floats)
#define PJWS 40                                 // W stage stride (floats)
#define PJ_XBYTES (64 * PJXS * 4)               // 9216
#define PJ_WBYTES (64 * PJWS * 4)               // 10240
#define PJ_STAGE (PJ_XBYTES + PJ_WBYTES)        // 19456 ; 2 stages = 38912

__global__ __launch_bounds__(128, 3) void fused_kernel(
    const float* __restrict__ x, const float* __restrict__ W,
    __half* __restrict__ kbuf, float* __restrict__ out,
    float* __restrict__ part, float* __restrict__ stats,
    int* __restrict__ pflags, int* __restrict__ tflags)
{
    extern __shared__ char smc[];
    const uint32_t sba = (uint32_t)__cvta_generic_to_shared(smc);

    const int tid = threadIdx.x;
    const int bid = blockIdx.x;
    const int rank = (bid < 148) ? bid : ((bid < 296) ? (443 - bid) : bid);
    const int w = tid >> 5, lane = tid & 31, gid = lane >> 2, t4 = lane & 3;

    // =============== PHASE 1: projection (ranks 128..383) ===============
    if (rank >= 128) {
        const int u = 383 - rank;               // 0..255, urgency order
        const int tile = (u & 7) * 32 + (u >> 3);
        const int prow0 = tile * 64;            // global row in [B*T)

        // 2-stage cp.async pipeline over 32 k-chunks of 32 cols
        auto pj_issue = [&](int ci) {
            uint32_t dx = sba + (uint32_t)((ci & 1) * PJ_STAGE);
            uint32_t dw = dx + PJ_XBYTES;
            const float* xsrc = x + (size_t)prow0 * CC + ci * 32;
            const float* wsrc = W + ci * 32;
            #pragma unroll
            for (int t = 0; t < 4; t++) {
                int i = tid + 128 * t;
                int r = i >> 3, c = i & 7;
                cpa16(dx + (uint32_t)(r * PJXS + c * 4) * 4,
                      xsrc + (size_t)r * CC + c * 4);
                cpa16(dw + (uint32_t)(r * PJWS + c * 4) * 4,
                      wsrc + (size_t)r * CC + c * 4);
            }
        };

        float acc[8][4];
        #pragma unroll
        for (int i = 0; i < 8; i++)
            #pragma unroll
            for (int l = 0; l < 4; l++) acc[i][l] = 0.f;

        pj_issue(0); cpa_commit();

        for (int ci = 0; ci < 32; ci++) {
            asm volatile("cp.async.wait_group 0;");
            __syncthreads();
            if (ci + 1 < 32) pj_issue(ci + 1);
            cpa_commit();

            const float* bx = (const float*)(smc + (ci & 1) * PJ_STAGE);
            const float* bw = (const float*)(smc + (ci & 1) * PJ_STAGE + PJ_XBYTES);
            #pragma unroll
            for (int c = 0; c < 2; c++) {      // two k16 steps
                uint32_t a[4];
                const float* p = bx + (16 * w + gid) * PJXS + 16 * c + 2 * t4;
                float2 u0 = *(const float2*)p;
                float2 u1 = *(const float2*)(p + 8 * PJXS);
                float2 u2 = *(const float2*)(p + 8);
                float2 u3 = *(const float2*)(p + 8 * PJXS + 8);
                a[0] = packh2(u0.x, u0.y);
                a[1] = packh2(u1.x, u1.y);
                a[2] = packh2(u2.x, u2.y);
                a[3] = packh2(u3.x, u3.y);
                #pragma unroll
                for (int nt = 0; nt < 8; nt++) {
                    const float* pw = bw + (8 * nt + gid) * PJWS + 16 * c + 2 * t4;
                    float2 w0 = *(const float2*)pw;
                    float2 w1 = *(const float2*)(pw + 8);
                    mma16(acc[nt], a, packh2(w0.x, w0.y), packh2(w1.x, w1.y));
                }
            }
            __syncthreads();   // stage consumed before next-next overwrite
        }

        // epilogue: fp16 natural layout
        #pragma unroll
        for (int nt = 0; nt < 8; nt++) {
            int r = prow0 + 16 * w + gid;
            int cb = 8 * nt + 2 * t4;
            *(__half2*)(kbuf + (size_t)r * HH + cb) =
                __floats2half2_rn(acc[nt][0], acc[nt][1]);
            *(__half2*)(kbuf + (size_t)(r + 8) * HH + cb) =
                __floats2half2_rn(acc[nt][2], acc[nt][3]);
        }
        __syncthreads();
        if (tid == 0) {
            __threadfence();
            atomicExch(&tflags[tile], 1);
        }
    }

    // =============== PHASE 2: attention ===============
    const int item = c_order[rank >> 3];
    const int b = rank & 7;
    const int tfb = b * 32;

    int qt, j0, j1, split;
    bool is_split;
    if (item < 32) {
        qt = 16 + (item >> 1);
        split = item & 1;
        int jm = qt >> 1;
        int h = (jm + 1) >> 1;
        if (split == 0) { j0 = 0; j1 = h - 1; }
        else            { j0 = h; j1 = jm; }
        is_split = true;
    } else {
        qt = item - 32;
        split = 0;
        j0 = 0; j1 = qt >> 1;
        is_split = false;
    }
    const int jmaskg = qt >> 1;
    const int qrow0 = qt * QT;
    const __half* kbase = kbuf + (size_t)b * TT * HH;

    const uint32_t sQa = sba;
    const uint32_t sKa = sba + QT * QS2 * 2;

    const uint32_t aQ_lane = sQa +
        (uint32_t)((16 * w + (lane & 15)) * QS2 + ((lane >> 4) << 3)) * 2;
    const uint32_t bK_lane = sKa +
        (uint32_t)((((lane & 7) + ((lane & 16) ? 8 : 0)) * KS2) + ((lane & 8) ? 8 : 0)) * 2;
    const uint32_t vV_lane = sKa +
        (uint32_t)((((lane & 7) + ((lane & 8) ? 8 : 0)) * KS2) + ((lane & 16) ? 8 : 0)) * 2;

    auto load_tile = [&](int j, int st) {
        #pragma unroll
        for (int t = 0; t < 8; t++) {
            int i = tid + t * 128;
            int r = i >> 3, c = i & 7;
            cpa16(sKa + (uint32_t)(st * KSTG + r * KS2 + c * 8) * 2,
                  kbase + (size_t)(j * KT + r) * HH + c * 8);
        }
    };

    // prologue: wait for Q tile + first K tile projection, then issue loads
    if (tid == 0) {
        while (atomicAdd(&tflags[tfb + qt], 0) == 0) __nanosleep(64);
        while (atomicAdd(&tflags[tfb + 2 * j0], 0) == 0) __nanosleep(64);
        while (atomicAdd(&tflags[tfb + 2 * j0 + 1], 0) == 0) __nanosleep(64);
    }
    __syncthreads();
    #pragma unroll
    for (int t = 0; t < 4; t++) {
        int i = tid + t * 128;
        int r = i >> 3, c = i & 7;
        cpa16(sQa + (uint32_t)(r * QS2 + c * 8) * 2,
              kbase + (size_t)(qrow0 + r) * HH + c * 8);
    }
    load_tile(j0, 0);
    cpa_commit();

    float m0 = -1e30f, m1 = -1e30f, l0 = 0.f, l1 = 0.f;
    const int rg0 = qrow0 + 16 * w + gid;
    const int rg1 = rg0 + 8;

    float o[8][4];
    #pragma unroll
    for (int i = 0; i < 8; i++)
        #pragma unroll
        for (int l = 0; l < 4; l++) o[i][l] = 0.f;

    for (int j = j0; j <= j1; j++) {
        const int st = (j - j0) & 1;
        if (tid == 0 && j < j1) {
            while (atomicAdd(&tflags[tfb + 2 * (j + 1)], 0) == 0) __nanosleep(64);
            while (atomicAdd(&tflags[tfb + 2 * (j + 1) + 1], 0) == 0) __nanosleep(64);
        }
        asm volatile("cp.async.wait_group 0;");
        __syncthreads();
        if (j < j1) load_tile(j + 1, st ^ 1);
        cpa_commit();
        const uint32_t stoff = (uint32_t)(st * KSTG) * 2;

        // ---- S = Q K^T ----
        float s[16][4];
        #pragma unroll
        for (int nt = 0; nt < 16; nt++)
            #pragma unroll
            for (int l = 0; l < 4; l++) s[nt][l] = 0.f;

        #pragma unroll
        for (int c = 0; c < 4; c++) {
            uint32_t a[4];
            ldsm4(a[0], a[1], a[2], a[3], aQ_lane + c * 32);
            #pragma unroll
            for (int a8 = 0; a8 < 8; a8++) {
                uint32_t b0, b1, b2, b3;
                ldsm4(b0, b1, b2, b3,
                      bK_lane + stoff + (uint32_t)(a8 * 16 * KS2) * 2 + c * 32);
                mma16(s[2 * a8],     a, b0, b1);
                mma16(s[2 * a8 + 1], a, b2, b3);
            }
        }

        // ---- causal mask (diagonal tile only) ----
        if (j == jmaskg) {
            #pragma unroll
            for (int nt = 0; nt < 16; nt++) {
                int kc = j * KT + 8 * nt + 2 * t4;
                if (kc     > rg0) s[nt][0] = -1e30f;
                if (kc + 1 > rg0) s[nt][1] = -1e30f;
                if (kc     > rg1) s[nt][2] = -1e30f;
                if (kc + 1 > rg1) s[nt][3] = -1e30f;
            }
        }

        // ---- online softmax ----
        float mx0 = -1e30f, mx1 = -1e30f;
        #pragma unroll
        for (int nt = 0; nt < 16; nt++) {
            mx0 = fmaxf(mx0, fmaxf(s[nt][0], s[nt][1]));
            mx1 = fmaxf(mx1, fmaxf(s[nt][2], s[nt][3]));
        }
        mx0 = fmaxf(mx0, __shfl_xor_sync(0xffffffffu, mx0, 1));
        mx0 = fmaxf(mx0, __shfl_xor_sync(0xffffffffu, mx0, 2));
        mx1 = fmaxf(mx1, __shfl_xor_sync(0xffffffffu, mx1, 1));
        mx1 = fmaxf(mx1, __shfl_xor_sync(0xffffffffu, mx1, 2));

        float mn0 = fmaxf(m0, mx0), mn1 = fmaxf(m1, mx1);
        float al0 = ex2f((m0 - mn0) * C1), al1 = ex2f((m1 - mn1) * C1);
        m0 = mn0; m1 = mn1;
        float mc0 = mn0 * C1, mc1 = mn1 * C1;

        uint32_t pa[8][4];
        #pragma unroll
        for (int nt = 0; nt < 16; nt++) {
            float t0 = s[nt][0] * C1 - mc0;
            float t1 = s[nt][1] * C1 - mc0;
            float t2 = s[nt][2] * C1 - mc1;
            float t3 = s[nt][3] * C1 - mc1;
            uint32_t u01 = h2ex2(packh2(t0, t1));
            uint32_t u23 = h2ex2(packh2(t2, t3));
            pa[nt >> 1][(nt & 1) * 2]     = u01;
            pa[nt >> 1][(nt & 1) * 2 + 1] = u23;
        }

        #pragma unroll
        for (int nt = 0; nt < 8; nt++) {
            o[nt][0] *= al0; o[nt][1] *= al0; o[nt][2] *= al1; o[nt][3] *= al1;
        }

        float lacc[4] = { 0.f, 0.f, 0.f, 0.f };
        #pragma unroll
        for (int kk = 0; kk < 8; kk++) {
            mma16(lacc, pa[kk], ONESH2, ONESH2);
            #pragma unroll
            for (int a2 = 0; a2 < 4; a2++) {
                uint32_t v0, v1, v2, v3;
                ldsm4t(v0, v1, v2, v3,
                       vV_lane + stoff + (uint32_t)(kk * 16 * KS2) * 2 + a2 * 32);
                mma16(o[2 * a2],     pa[kk], v0, v1);
                mma16(o[2 * a2 + 1], pa[kk], v2, v3);
            }
        }
        l0 = l0 * al0 + lacc[0];
        l1 = l1 * al1 + lacc[2];
    }

    const int lr0 = 16 * w + gid, lr1 = lr0 + 8;

    if (!is_split) {
        float il0 = 1.f / l0, il1 = 1.f / l1;
        float* ob = out + (size_t)b * TT * HH;
        #pragma unroll
        for (int nt = 0; nt < 8; nt++) {
            int c = 8 * nt + 2 * t4;
            float2 r0v = { o[nt][0] * il0, o[nt][1] * il0 };
            float2 r1v = { o[nt][2] * il1, o[nt][3] * il1 };
            *(float2*)(ob + (size_t)rg0 * HH + c) = r0v;
            *(float2*)(ob + (size_t)rg1 * HH + c) = r1v;
        }
    } else if (split == 0) {
        const int pair = b * 16 + (qt - 16);
        float* po = part + (size_t)pair * (QT * HH);
        #pragma unroll
        for (int nt = 0; nt < 8; nt++) {
            int c = 8 * nt + 2 * t4;
            float2 r0v = { o[nt][0], o[nt][1] };
            float2 r1v = { o[nt][2], o[nt][3] };
            *(float2*)(po + lr0 * HH + c) = r0v;
            *(float2*)(po + lr1 * HH + c) = r1v;
        }
        if (t4 == 0) {
            stats[pair * 128 + lr0 * 2]     = m0;
            stats[pair * 128 + lr0 * 2 + 1] = l0;
            stats[pair * 128 + lr1 * 2]     = m1;
            stats[pair * 128 + lr1 * 2 + 1] = l1;
        }
        __syncthreads();
        if (tid == 0) {
            __threadfence();
            atomicExch(&pflags[pair], 1);
        }
    } else {
        const int pair = b * 16 + (qt - 16);
        if (tid == 0) {
            while (atomicAdd(&pflags[pair], 0) == 0) __nanosleep(32);
        }
        __syncthreads();
        __threadfence();

        const float* po = part + (size_t)pair * (QT * HH);
        float2 st0 = __ldcg((const float2*)&stats[pair * 128 + lr0 * 2]);
        float2 st1 = __ldcg((const float2*)&stats[pair * 128 + lr1 * 2]);

        float mm0 = fmaxf(st0.x, m0);
        float a00 = ex2f((st0.x - mm0) * C1), a01 = ex2f((m0 - mm0) * C1);
        float iv0 = 1.f / (a00 * st0.y + a01 * l0);
        float mm1 = fmaxf(st1.x, m1);
        float a10 = ex2f((st1.x - mm1) * C1), a11 = ex2f((m1 - mm1) * C1);
        float iv1 = 1.f / (a10 * st1.y + a11 * l1);

        float* ob = out + (size_t)b * TT * HH;
        #pragma unroll
        for (int nt = 0; nt < 8; nt++) {
            int c = 8 * nt + 2 * t4;
            float2 ua = __ldcg((const float2*)(po + lr0 * HH + c));
            float2 ub = __ldcg((const float2*)(po + lr1 * HH + c));
            float2 r0v = { (a00 * ua.x + a01 * o[nt][0]) * iv0,
                           (a00 * ua.y + a01 * o[nt][1]) * iv0 };
            float2 r1v = { (a10 * ub.x + a11 * o[nt][2]) * iv1,
                           (a10 * ub.y + a11 * o[nt][3]) * iv1 };
            *(float2*)(ob + (size_t)rg0 * HH + c) = r0v;
            *(float2*)(ob + (size_t)rg1 * HH + c) = r1v;
        }
        __syncthreads();
        if (tid == 0) pflags[pair] = 0;
    }
}

// ---------------------------------------------------------------------------
// launch
// ---------------------------------------------------------------------------
extern "C" void kernel_launch(void* const* d_in, const int* in_sizes, int n_in,
                              void* d_out, int out_size)
{
    const float* x = (const float*)d_in[0];   // [B, T, C]
    const float* W = (const float*)d_in[1];   // [H, C]
    float* out = (float*)d_out;               // [B, T, H]

    __half* kbuf = nullptr;
    float *part = nullptr, *stats = nullptr;
    int *pflags = nullptr, *tflags = nullptr;
    cudaGetSymbolAddress((void**)&kbuf, g_kbuf);
    cudaGetSymbolAddress((void**)&part, g_part);
    cudaGetSymbolAddress((void**)&stats, g_stats);
    cudaGetSymbolAddress((void**)&pflags, g_pflags);
    cudaGetSymbolAddress((void**)&tflags, g_tflags);

    cudaFuncSetAttribute(fused_kernel, cudaFuncAttributeMaxDynamicSharedMemorySize,
                         FUSED_SMEM_BYTES);

    reset_kernel<<<1, 256>>>(tflags);

    fused_kernel<<<384, 128, FUSED_SMEM_BYTES>>>(x, W, kbuf, out,
                                                 part, stats, pflags, tflags);
}

// round 15
// speedup vs baseline: 1.0603x; 1.0603x over previous
#include <cuda_runtime.h>
#include <cuda_fp16.h>
#include <cstdint>

// Problem constants
#define BB 8
#define TT 2048
#define CC 1024
#define HH 64

// k projection scratch: fp16, NATURAL layout
__device__ __half g_kbuf[BB * TT * HH];
// KV-split partials (split-0) + per-row (m,l) + ready flags
__device__ float g_part[128 * 64 * 64];
__device__ float g_stats[128 * 64 * 2];
__device__ int g_flags[128];

// item order sorted by iteration count (descending), 48 items per batch
__constant__ int c_order[48] = {
    46,47,25,27,28,29,30,31,                 // 8 iters
    44,45,17,19,20,21,22,23,24,26,           // 7
    42,43, 9,11,12,13,14,15,16,18,           // 6
    40,41, 1, 3, 4, 5, 6, 7, 8,10,           // 5
    38,39, 0, 2,                             // 4
    36,37, 34,35, 32,33                      // 3,2,1
};

// ---------------------------------------------------------------------------
// helpers
// ---------------------------------------------------------------------------
__device__ __forceinline__ void mma16(float* c, const uint32_t* a,
                                      uint32_t b0, uint32_t b1) {
    asm volatile(
        "mma.sync.aligned.m16n8k16.row.col.f32.f16.f16.f32 "
        "{%0,%1,%2,%3}, {%4,%5,%6,%7}, {%8,%9}, {%0,%1,%2,%3};"
        : "+f"(c[0]), "+f"(c[1]), "+f"(c[2]), "+f"(c[3])
        : "r"(a[0]), "r"(a[1]), "r"(a[2]), "r"(a[3]), "r"(b0), "r"(b1));
}

__device__ __forceinline__ void ldsm4(uint32_t& r0, uint32_t& r1, uint32_t& r2,
                                      uint32_t& r3, uint32_t addr) {
    asm volatile("ldmatrix.sync.aligned.m8n8.x4.shared.b16 {%0,%1,%2,%3}, [%4];"
                 : "=r"(r0), "=r"(r1), "=r"(r2), "=r"(r3) : "r"(addr));
}

__device__ __forceinline__ void ldsm4t(uint32_t& r0, uint32_t& r1, uint32_t& r2,
                                       uint32_t& r3, uint32_t addr) {
    asm volatile("ldmatrix.sync.aligned.m8n8.x4.trans.shared.b16 {%0,%1,%2,%3}, [%4];"
                 : "=r"(r0), "=r"(r1), "=r"(r2), "=r"(r3) : "r"(addr));
}

__device__ __forceinline__ uint32_t packh2(float lo, float hi) {
    uint32_t d;
    asm("cvt.rn.f16x2.f32 %0, %1, %2;" : "=r"(d) : "f"(hi), "f"(lo));
    return d;
}

__device__ __forceinline__ float ex2f(float x) {
    float y;
    asm("ex2.approx.ftz.f32 %0, %1;" : "=f"(y) : "f"(x));
    return y;
}

__device__ __forceinline__ uint32_t h2ex2(uint32_t x) {
    uint32_t y;
    asm("ex2.approx.f16x2 %0, %1;" : "=r"(y) : "r"(x));
    return y;
}

__device__ __forceinline__ void cpa16(uint32_t dst, const void* src) {
    asm volatile("cp.async.cg.shared.global [%0], [%1], 16;" :: "r"(dst), "l"(src));
}
__device__ __forceinline__ void cpa_commit() {
    asm volatile("cp.async.commit_group;");
}

// ---------------------------------------------------------------------------
// Kernel 1: k = fp16(x @ W^T). fp16 m16n8k16 datapath; W read as fp32 and
// converted in-register at B-frag build (same RN rounding as a pre-pass).
// 64 rows/block -> grid 256, 2 CTAs/SM (16 warps/SM). 256 threads = 8 warps
// (4 m-groups of 16 rows x 2 n-groups of 32 cols). 4-stage cp.async.
// ---------------------------------------------------------------------------
#define PROJ_M 64
#define PKC 32
#define XS 36                                   // x stage stride (floats)
#define WFS 40                                  // W fp32 stage stride (floats)
#define PST 4
#define X_STAGE_BYTES (PROJ_M * XS * 4)         // 9216
#define W_STAGE_BYTES (HH * WFS * 4)            // 10240
#define STAGE_BYTES (X_STAGE_BYTES + W_STAGE_BYTES)  // 19456
#define PROJ_SMEM_BYTES (PST * STAGE_BYTES)     // 77824

__global__ __launch_bounds__(256, 2) void proj_kernel(
    const float* __restrict__ x, const float* __restrict__ W, __half* __restrict__ ko)
{
    extern __shared__ char psm[];
    const uint32_t sba = (uint32_t)__cvta_generic_to_shared(psm);

    const int tid = threadIdx.x;
    const int row0 = blockIdx.x * PROJ_M;
    const int w = tid >> 5, lane = tid & 31, gid = lane >> 2, t4 = lane & 3;
    const int mw = w & 3;      // m-group: 16 rows at 16*mw
    const int nh = w >> 2;     // n-group: 32 cols at 32*nh

    // loaders: x tile 64x32 = 512 float4 -> 2/thread; W same
    const int r0 = tid >> 3, c0 = tid & 7;
    const int r1 = (tid + 256) >> 3, c1 = (tid + 256) & 7;

    auto issue_chunk = [&](int ci) {
        int st = ci & (PST - 1);
        uint32_t dx = sba + (uint32_t)(st * STAGE_BYTES);
        uint32_t dw = dx + X_STAGE_BYTES;
        const float* xsrc = x + (size_t)row0 * CC + ci * PKC;
        const float* wsrc = W + ci * PKC;
        cpa16(dx + (uint32_t)(r0 * XS + c0 * 4) * 4, xsrc + (size_t)r0 * CC + c0 * 4);
        cpa16(dx + (uint32_t)(r1 * XS + c1 * 4) * 4, xsrc + (size_t)r1 * CC + c1 * 4);
        cpa16(dw + (uint32_t)(r0 * WFS + c0 * 4) * 4, wsrc + (size_t)r0 * CC + c0 * 4);
        cpa16(dw + (uint32_t)(r1 * WFS + c1 * 4) * 4, wsrc + (size_t)r1 * CC + c1 * 4);
    };

    float acc[4][4];
    #pragma unroll
    for (int i = 0; i < 4; i++)
        #pragma unroll
        for (int l = 0; l < 4; l++) acc[i][l] = 0.f;

    issue_chunk(0); cpa_commit();
    issue_chunk(1); cpa_commit();
    issue_chunk(2); cpa_commit();

    const int NCHUNK = CC / PKC;  // 32
    for (int ci = 0; ci < NCHUNK; ci++) {
        asm volatile("cp.async.wait_group 2;");
        __syncthreads();
        if (ci + 3 < NCHUNK) issue_chunk(ci + 3);
        cpa_commit();

        const int st = ci & (PST - 1);
        const float* bx = (const float*)(psm + st * STAGE_BYTES);
        const float* bw = (const float*)(psm + st * STAGE_BYTES + X_STAGE_BYTES);

        #pragma unroll
        for (int c = 0; c < 2; c++) {          // two k16 steps per 32-k chunk
            uint32_t a[4];
            const float* p = bx + (16 * mw + gid) * XS + 16 * c + 2 * t4;
            float2 u0 = *(const float2*)p;
            float2 u1 = *(const float2*)(p + 8 * XS);
            float2 u2 = *(const float2*)(p + 8);
            float2 u3 = *(const float2*)(p + 8 * XS + 8);
            a[0] = packh2(u0.x, u0.y);
            a[1] = packh2(u1.x, u1.y);
            a[2] = packh2(u2.x, u2.y);
            a[3] = packh2(u3.x, u3.y);
            #pragma unroll
            for (int nt = 0; nt < 4; nt++) {   // four n8 tiles
                const float* pw = bw + (32 * nh + 8 * nt + gid) * WFS + 16 * c + 2 * t4;
                float2 w0 = *(const float2*)pw;
                float2 w1 = *(const float2*)(pw + 8);
                mma16(acc[nt], a, packh2(w0.x, w0.y), packh2(w1.x, w1.y));
            }
        }
    }

    // epilogue: fp16, natural columns
    #pragma unroll
    for (int nt = 0; nt < 4; nt++) {
        int r = row0 + 16 * mw + gid;
        int cb = 32 * nh + 8 * nt + 2 * t4;
        *(__half2*)(ko + (size_t)r * HH + cb) =
            __floats2half2_rn(acc[nt][0], acc[nt][1]);
        *(__half2*)(ko + (size_t)(r + 8) * HH + cb) =
            __floats2half2_rn(acc[nt][2], acc[nt][3]);
    }
}

// ---------------------------------------------------------------------------
// Kernel 2: causal flash attention (R11 verbatim): fp16 + m16n8k16 + ldmatrix,
// softmax via ex2.f16x2, l via ones-mma, fused KV-split combine.
// ---------------------------------------------------------------------------
#define QT 64
#define KT 128
#define QS2 72
#define KS2 72
#define C1 0.0450842200277801f   // log2(e) / 32
#define ONESH2 0x3C003C00u

#define ATTN_SMEM_BYTES ((QT * QS2 + KT * KS2) * 2)

__global__ __launch_bounds__(128, 3) void attn_kernel(
    const __half* __restrict__ kb, float* __restrict__ out,
    float* __restrict__ part, float* __restrict__ stats, int* __restrict__ flags)
{
    extern __shared__ __half smh[];
    __half* sQ = smh;                 // QT x QS2
    __half* sK = smh + QT * QS2;      // KT x KS2
    const uint32_t sQa = (uint32_t)__cvta_generic_to_shared(sQ);
    const uint32_t sKa = (uint32_t)__cvta_generic_to_shared(sK);

    const int tid = threadIdx.x;
    const int bid = blockIdx.x;
    const int rank = (bid < 148) ? bid : ((bid < 296) ? (443 - bid) : bid);
    const int item = c_order[rank >> 3];
    const int b = rank & 7;

    int qt, j0, j1, split;
    bool is_split;
    if (item < 32) {
        qt = 16 + (item >> 1);
        split = item & 1;
        int jm = qt >> 1;
        int h = (jm + 1) >> 1;
        if (split == 0) { j0 = 0; j1 = h - 1; }
        else            { j0 = h; j1 = jm; }
        is_split = true;
    } else {
        qt = item - 32;
        split = 0;
        j0 = 0; j1 = qt >> 1;
        is_split = false;
    }
    const int jmaskg = qt >> 1;
    const int qrow0 = qt * QT;
    const __half* kbase = kb + (size_t)b * TT * HH;

    const int w = tid >> 5, lane = tid & 31, gid = lane >> 2, t4 = lane & 3;

    const uint32_t aQ_lane = sQa +
        (uint32_t)((16 * w + (lane & 15)) * QS2 + ((lane >> 4) << 3)) * 2;
    const uint32_t bK_lane = sKa +
        (uint32_t)((((lane & 7) + ((lane & 16) ? 8 : 0)) * KS2) + ((lane & 8) ? 8 : 0)) * 2;
    const uint32_t vV_lane = sKa +
        (uint32_t)((((lane & 7) + ((lane & 8) ? 8 : 0)) * KS2) + ((lane & 16) ? 8 : 0)) * 2;

    // load Q tile (plain copy; 1/32 scale folded into exp via C1)
    #pragma unroll
    for (int i = tid; i < QT * (HH / 8); i += 128) {
        int r = i >> 3, c = i & 7;
        *(uint4*)&sQ[r * QS2 + c * 8] =
            *(const uint4*)(kbase + (size_t)(qrow0 + r) * HH + c * 8);
    }

    float m0 = -1e30f, m1 = -1e30f, l0 = 0.f, l1 = 0.f;
    const int rg0 = qrow0 + 16 * w + gid;
    const int rg1 = rg0 + 8;

    float o[8][4];
    #pragma unroll
    for (int i = 0; i < 8; i++)
        #pragma unroll
        for (int l = 0; l < 4; l++) o[i][l] = 0.f;

    for (int j = j0; j <= j1; j++) {
        __syncthreads();
        #pragma unroll
        for (int i = tid; i < KT * (HH / 8); i += 128) {
            int r = i >> 3, c = i & 7;
            *(uint4*)&sK[r * KS2 + c * 8] =
                *(const uint4*)(kbase + (size_t)(j * KT + r) * HH + c * 8);
        }
        __syncthreads();

        // ---- S = Q K^T ----
        float s[16][4];
        #pragma unroll
        for (int nt = 0; nt < 16; nt++)
            #pragma unroll
            for (int l = 0; l < 4; l++) s[nt][l] = 0.f;

        #pragma unroll
        for (int c = 0; c < 4; c++) {
            uint32_t a[4];
            ldsm4(a[0], a[1], a[2], a[3], aQ_lane + c * 32);
            #pragma unroll
            for (int a8 = 0; a8 < 8; a8++) {
                uint32_t b0, b1, b2, b3;
                ldsm4(b0, b1, b2, b3,
                      bK_lane + (uint32_t)(a8 * 16 * KS2) * 2 + c * 32);
                mma16(s[2 * a8],     a, b0, b1);
                mma16(s[2 * a8 + 1], a, b2, b3);
            }
        }

        // ---- causal mask (diagonal tile only) ----
        if (j == jmaskg) {
            #pragma unroll
            for (int nt = 0; nt < 16; nt++) {
                int kc = j * KT + 8 * nt + 2 * t4;
                if (kc     > rg0) s[nt][0] = -1e30f;
                if (kc + 1 > rg0) s[nt][1] = -1e30f;
                if (kc     > rg1) s[nt][2] = -1e30f;
                if (kc + 1 > rg1) s[nt][3] = -1e30f;
            }
        }

        // ---- online softmax ----
        float mx0 = -1e30f, mx1 = -1e30f;
        #pragma unroll
        for (int nt = 0; nt < 16; nt++) {
            mx0 = fmaxf(mx0, fmaxf(s[nt][0], s[nt][1]));
            mx1 = fmaxf(mx1, fmaxf(s[nt][2], s[nt][3]));
        }
        mx0 = fmaxf(mx0, __shfl_xor_sync(0xffffffffu, mx0, 1));
        mx0 = fmaxf(mx0, __shfl_xor_sync(0xffffffffu, mx0, 2));
        mx1 = fmaxf(mx1, __shfl_xor_sync(0xffffffffu, mx1, 1));
        mx1 = fmaxf(mx1, __shfl_xor_sync(0xffffffffu, mx1, 2));

        float mn0 = fmaxf(m0, mx0), mn1 = fmaxf(m1, mx1);
        float al0 = ex2f((m0 - mn0) * C1), al1 = ex2f((m1 - mn1) * C1);
        m0 = mn0; m1 = mn1;
        float mc0 = mn0 * C1, mc1 = mn1 * C1;

        // P = 2^(s*C1 - mc) via ex2.f16x2; lands directly in PV A-frag layout
        uint32_t pa[8][4];
        #pragma unroll
        for (int nt = 0; nt < 16; nt++) {
            float t0 = s[nt][0] * C1 - mc0;
            float t1 = s[nt][1] * C1 - mc0;
            float t2 = s[nt][2] * C1 - mc1;
            float t3 = s[nt][3] * C1 - mc1;
            uint32_t u01 = h2ex2(packh2(t0, t1));
            uint32_t u23 = h2ex2(packh2(t2, t3));
            pa[nt >> 1][(nt & 1) * 2]     = u01;
            pa[nt >> 1][(nt & 1) * 2 + 1] = u23;
        }

        #pragma unroll
        for (int nt = 0; nt < 8; nt++) {
            o[nt][0] *= al0; o[nt][1] *= al0; o[nt][2] *= al1; o[nt][3] *= al1;
        }

        // ---- O += P V ; l-partials via mma against ones-B ----
        float lacc[4] = { 0.f, 0.f, 0.f, 0.f };
        #pragma unroll
        for (int kk = 0; kk < 8; kk++) {
            mma16(lacc, pa[kk], ONESH2, ONESH2);
            #pragma unroll
            for (int a2 = 0; a2 < 4; a2++) {
                uint32_t v0, v1, v2, v3;
                ldsm4t(v0, v1, v2, v3,
                       vV_lane + (uint32_t)(kk * 16 * KS2) * 2 + a2 * 32);
                mma16(o[2 * a2],     pa[kk], v0, v1);
                mma16(o[2 * a2 + 1], pa[kk], v2, v3);
            }
        }
        l0 = l0 * al0 + lacc[0];
        l1 = l1 * al1 + lacc[2];
    }

    const int lr0 = 16 * w + gid, lr1 = lr0 + 8;

    if (!is_split) {
        float il0 = 1.f / l0, il1 = 1.f / l1;
        float* ob = out + (size_t)b * TT * HH;
        #pragma unroll
        for (int nt = 0; nt < 8; nt++) {
            int c = 8 * nt + 2 * t4;
            float2 r0v = { o[nt][0] * il0, o[nt][1] * il0 };
            float2 r1v = { o[nt][2] * il1, o[nt][3] * il1 };
            *(float2*)(ob + (size_t)rg0 * HH + c) = r0v;
            *(float2*)(ob + (size_t)rg1 * HH + c) = r1v;
        }
    } else if (split == 0) {
        const int pair = b * 16 + (qt - 16);
        float* po = part + (size_t)pair * (QT * HH);
        #pragma unroll
        for (int nt = 0; nt < 8; nt++) {
            int c = 8 * nt + 2 * t4;
            float2 r0v = { o[nt][0], o[nt][1] };
            float2 r1v = { o[nt][2], o[nt][3] };
            *(float2*)(po + lr0 * HH + c) = r0v;
            *(float2*)(po + lr1 * HH + c) = r1v;
        }
        if (t4 == 0) {
            stats[pair * 128 + lr0 * 2]     = m0;
            stats[pair * 128 + lr0 * 2 + 1] = l0;
            stats[pair * 128 + lr1 * 2]     = m1;
            stats[pair * 128 + lr1 * 2 + 1] = l1;
        }
        __syncthreads();
        if (tid == 0) {
            __threadfence();
            atomicExch(&flags[pair], 1);
        }
    } else {
        const int pair = b * 16 + (qt - 16);
        if (tid == 0) {
            while (atomicAdd(&flags[pair], 0) == 0) __nanosleep(32);
        }
        __syncthreads();
        __threadfence();

        const float* po = part + (size_t)pair * (QT * HH);
        float2 st0 = __ldcg((const float2*)&stats[pair * 128 + lr0 * 2]);
        float2 st1 = __ldcg((const float2*)&stats[pair * 128 + lr1 * 2]);

        float mm0 = fmaxf(st0.x, m0);
        float a00 = ex2f((st0.x - mm0) * C1), a01 = ex2f((m0 - mm0) * C1);
        float iv0 = 1.f / (a00 * st0.y + a01 * l0);
        float mm1 = fmaxf(st1.x, m1);
        float a10 = ex2f((st1.x - mm1) * C1), a11 = ex2f((m1 - mm1) * C1);
        float iv1 = 1.f / (a10 * st1.y + a11 * l1);

        float* ob = out + (size_t)b * TT * HH;
        #pragma unroll
        for (int nt = 0; nt < 8; nt++) {
            int c = 8 * nt + 2 * t4;
            float2 ua = __ldcg((const float2*)(po + lr0 * HH + c));
            float2 ub = __ldcg((const float2*)(po + lr1 * HH + c));
            float2 r0v = { (a00 * ua.x + a01 * o[nt][0]) * iv0,
                           (a00 * ua.y + a01 * o[nt][1]) * iv0 };
            float2 r1v = { (a10 * ub.x + a11 * o[nt][2]) * iv1,
                           (a10 * ub.y + a11 * o[nt][3]) * iv1 };
            *(float2*)(ob + (size_t)rg0 * HH + c) = r0v;
            *(float2*)(ob + (size_t)rg1 * HH + c) = r1v;
        }
        __syncthreads();
        if (tid == 0) flags[pair] = 0;
    }
}

// ---------------------------------------------------------------------------
// launch
// ---------------------------------------------------------------------------
extern "C" void kernel_launch(void* const* d_in, const int* in_sizes, int n_in,
                              void* d_out, int out_size)
{
    const float* x = (const float*)d_in[0];   // [B, T, C]
    const float* W = (const float*)d_in[1];   // [H, C]
    float* out = (float*)d_out;               // [B, T, H]

    __half* kbuf = nullptr;
    float *part = nullptr, *stats = nullptr;
    int* flags = nullptr;
    cudaGetSymbolAddress((void**)&kbuf, g_kbuf);
    cudaGetSymbolAddress((void**)&part, g_part);
    cudaGetSymbolAddress((void**)&stats, g_stats);
    cudaGetSymbolAddress((void**)&flags, g_flags);

    cudaFuncSetAttribute(proj_kernel, cudaFuncAttributeMaxDynamicSharedMemorySize,
                         PROJ_SMEM_BYTES);
    cudaFuncSetAttribute(attn_kernel, cudaFuncAttributeMaxDynamicSharedMemorySize,
                         ATTN_SMEM_BYTES);

    proj_kernel<<<(BB * TT) / PROJ_M, 256, PROJ_SMEM_BYTES>>>(x, W, kbuf);

    attn_kernel<<<384, 128, ATTN_SMEM_BYTES>>>(kbuf, out, part, stats, flags);
}

// round 16
// speedup vs baseline: 1.1826x; 1.1153x over previous
#include <cuda_runtime.h>
#include <cuda_fp16.h>
#include <cstdint>

// Problem constants
#define BB 8
#define TT 2048
#define CC 1024
#define HH 64

// k projection scratch: fp16, NATURAL layout
__device__ __half g_kbuf[BB * TT * HH];
// W pre-converted to fp16, natural layout [H, C]
__device__ __half g_wt[HH * CC];
// KV-split partials (split-0) + per-row (m,l) + ready flags
__device__ float g_part[128 * 64 * 64];
__device__ float g_stats[128 * 64 * 2];
__device__ int g_flags[128];

// item order sorted by iteration count (descending), 48 items per batch
__constant__ int c_order[48] = {
    46,47,25,27,28,29,30,31,                 // 8 iters
    44,45,17,19,20,21,22,23,24,26,           // 7
    42,43, 9,11,12,13,14,15,16,18,           // 6
    40,41, 1, 3, 4, 5, 6, 7, 8,10,           // 5
    38,39, 0, 2,                             // 4
    36,37, 34,35, 32,33                      // 3,2,1
};

// ---------------------------------------------------------------------------
// helpers
// ---------------------------------------------------------------------------
__device__ __forceinline__ void mma16(float* c, const uint32_t* a,
                                      uint32_t b0, uint32_t b1) {
    asm volatile(
        "mma.sync.aligned.m16n8k16.row.col.f32.f16.f16.f32 "
        "{%0,%1,%2,%3}, {%4,%5,%6,%7}, {%8,%9}, {%0,%1,%2,%3};"
        : "+f"(c[0]), "+f"(c[1]), "+f"(c[2]), "+f"(c[3])
        : "r"(a[0]), "r"(a[1]), "r"(a[2]), "r"(a[3]), "r"(b0), "r"(b1));
}

__device__ __forceinline__ void ldsm4(uint32_t& r0, uint32_t& r1, uint32_t& r2,
                                      uint32_t& r3, uint32_t addr) {
    asm volatile("ldmatrix.sync.aligned.m8n8.x4.shared.b16 {%0,%1,%2,%3}, [%4];"
                 : "=r"(r0), "=r"(r1), "=r"(r2), "=r"(r3) : "r"(addr));
}

__device__ __forceinline__ void ldsm4t(uint32_t& r0, uint32_t& r1, uint32_t& r2,
                                       uint32_t& r3, uint32_t addr) {
    asm volatile("ldmatrix.sync.aligned.m8n8.x4.trans.shared.b16 {%0,%1,%2,%3}, [%4];"
                 : "=r"(r0), "=r"(r1), "=r"(r2), "=r"(r3) : "r"(addr));
}

__device__ __forceinline__ uint32_t packh2(float lo, float hi) {
    uint32_t d;
    asm("cvt.rn.f16x2.f32 %0, %1, %2;" : "=r"(d) : "f"(hi), "f"(lo));
    return d;
}

__device__ __forceinline__ float ex2f(float x) {
    float y;
    asm("ex2.approx.ftz.f32 %0, %1;" : "=f"(y) : "f"(x));
    return y;
}

__device__ __forceinline__ uint32_t h2ex2(uint32_t x) {
    uint32_t y;
    asm("ex2.approx.f16x2 %0, %1;" : "=r"(y) : "r"(x));
    return y;
}

__device__ __forceinline__ void cpa16(uint32_t dst, const void* src) {
    asm volatile("cp.async.cg.shared.global [%0], [%1], 16;" :: "r"(dst), "l"(src));
}
__device__ __forceinline__ void cpa_commit() {
    asm volatile("cp.async.commit_group;");
}

// ---------------------------------------------------------------------------
// Kernel 0: W [64,1024] fp32 -> fp16, natural layout.
// ---------------------------------------------------------------------------
__global__ __launch_bounds__(128) void wconv_kernel(
    const float* __restrict__ W, __half* __restrict__ wt)
{
    const int i = blockIdx.x * 128 + threadIdx.x;   // 16384 float4 tasks
    float4 v = ((const float4*)W)[i];
    ((__half2*)wt)[2 * i]     = __floats2half2_rn(v.x, v.y);
    ((__half2*)wt)[2 * i + 1] = __floats2half2_rn(v.z, v.w);
}

// ---------------------------------------------------------------------------
// Kernel 1: k = fp16(x @ W^T), fp16 m16n8k16 datapath (R11 layout) at
// PROJ_M=64: grid 256, 2 CTAs/SM, 16 warps/SM. x fp32 (A: LDS.64+cvt);
// W fp16 (B: ldmatrix). 4-stage cp.async over 32-col K chunks.
// ---------------------------------------------------------------------------
#define PROJ_M 64
#define PKC 32
#define XS 36                                   // x stage stride (floats)
#define WH 40                                   // W fp16 stage stride (halves)
#define PST 4
#define X_STAGE_BYTES (PROJ_M * XS * 4)         // 9216
#define W_STAGE_BYTES (HH * WH * 2)             // 5120
#define STAGE_BYTES (X_STAGE_BYTES + W_STAGE_BYTES)  // 14336
#define PROJ_SMEM_BYTES (PST * STAGE_BYTES)     // 57344

__global__ __launch_bounds__(256, 2) void proj_kernel(
    const float* __restrict__ x, const __half* __restrict__ wt, __half* __restrict__ ko)
{
    extern __shared__ char psm[];
    const uint32_t sba = (uint32_t)__cvta_generic_to_shared(psm);

    const int tid = threadIdx.x;
    const int row0 = blockIdx.x * PROJ_M;
    const int w = tid >> 5, lane = tid & 31, gid = lane >> 2, t4 = lane & 3;
    const int mw = w & 3;      // m-group: 16 rows at 16*mw
    const int nh = w >> 2;     // n-group: 32 cols at 32*nh

    // x loader: 512 float4 tasks -> 2/thread; W loader: 256 16B tasks -> 1/thread
    const int xr0 = tid >> 3, xc0 = tid & 7;
    const int xr1 = (tid + 256) >> 3, xc1 = (tid + 256) & 7;
    const int wr = tid >> 2, wc = tid & 3;

    auto issue_chunk = [&](int ci) {
        int st = ci & (PST - 1);
        uint32_t dx = sba + (uint32_t)(st * STAGE_BYTES);
        uint32_t dw = dx + X_STAGE_BYTES;
        const float* xsrc = x + (size_t)row0 * CC + ci * PKC;
        const __half* wsrc = wt + ci * PKC;
        cpa16(dx + (uint32_t)(xr0 * XS + xc0 * 4) * 4, xsrc + (size_t)xr0 * CC + xc0 * 4);
        cpa16(dx + (uint32_t)(xr1 * XS + xc1 * 4) * 4, xsrc + (size_t)xr1 * CC + xc1 * 4);
        cpa16(dw + (uint32_t)(wr * WH + wc * 8) * 2, wsrc + (size_t)wr * CC + wc * 8);
    };

    // ldmatrix lane address components for W B-frags
    const int bRow = (lane & 7) + ((lane & 16) ? 8 : 0);
    const int bColB = (lane & 8) ? 8 : 0;

    float acc[4][4];
    #pragma unroll
    for (int i = 0; i < 4; i++)
        #pragma unroll
        for (int l = 0; l < 4; l++) acc[i][l] = 0.f;

    issue_chunk(0); cpa_commit();
    issue_chunk(1); cpa_commit();
    issue_chunk(2); cpa_commit();

    const int NCHUNK = CC / PKC;  // 32
    for (int ci = 0; ci < NCHUNK; ci++) {
        asm volatile("cp.async.wait_group 2;");
        __syncthreads();
        if (ci + 3 < NCHUNK) issue_chunk(ci + 3);
        cpa_commit();

        const int st = ci & (PST - 1);
        const float* bx = (const float*)(psm + st * STAGE_BYTES);
        const uint32_t bwa = sba + (uint32_t)(st * STAGE_BYTES) + X_STAGE_BYTES;

        #pragma unroll
        for (int c = 0; c < 2; c++) {          // two k16 steps per 32-k chunk
            uint32_t a[4];
            const float* p = bx + (16 * mw + gid) * XS + 16 * c + 2 * t4;
            float2 u0 = *(const float2*)p;
            float2 u1 = *(const float2*)(p + 8 * XS);
            float2 u2 = *(const float2*)(p + 8);
            float2 u3 = *(const float2*)(p + 8 * XS + 8);
            a[0] = packh2(u0.x, u0.y);
            a[1] = packh2(u1.x, u1.y);
            a[2] = packh2(u2.x, u2.y);
            a[3] = packh2(u3.x, u3.y);
            #pragma unroll
            for (int g = 0; g < 2; g++) {      // two 16-n groups
                uint32_t b0, b1, b2, b3;
                uint32_t baddr = bwa +
                    (uint32_t)((32 * nh + 16 * g + bRow) * WH + 16 * c + bColB) * 2;
                ldsm4(b0, b1, b2, b3, baddr);
                mma16(acc[2 * g],     a, b0, b1);
                mma16(acc[2 * g + 1], a, b2, b3);
            }
        }
    }

    // epilogue: fp16, natural columns
    #pragma unroll
    for (int nt = 0; nt < 4; nt++) {
        int r = row0 + 16 * mw + gid;
        int cb = 32 * nh + 8 * nt + 2 * t4;
        *(__half2*)(ko + (size_t)r * HH + cb) =
            __floats2half2_rn(acc[nt][0], acc[nt][1]);
        *(__half2*)(ko + (size_t)(r + 8) * HH + cb) =
            __floats2half2_rn(acc[nt][2], acc[nt][3]);
    }
}

// ---------------------------------------------------------------------------
// Kernel 2: causal flash attention (R11 verbatim): fp16 + m16n8k16 + ldmatrix,
// softmax via ex2.f16x2, l via ones-mma, fused KV-split combine.
// ---------------------------------------------------------------------------
#define QT 64
#define KT 128
#define QS2 72
#define KS2 72
#define C1 0.0450842200277801f   // log2(e) / 32
#define ONESH2 0x3C003C00u

#define ATTN_SMEM_BYTES ((QT * QS2 + KT * KS2) * 2)

__global__ __launch_bounds__(128, 3) void attn_kernel(
    const __half* __restrict__ kb, float* __restrict__ out,
    float* __restrict__ part, float* __restrict__ stats, int* __restrict__ flags)
{
    extern __shared__ __half smh[];
    __half* sQ = smh;                 // QT x QS2
    __half* sK = smh + QT * QS2;      // KT x KS2
    const uint32_t sQa = (uint32_t)__cvta_generic_to_shared(sQ);
    const uint32_t sKa = (uint32_t)__cvta_generic_to_shared(sK);

    const int tid = threadIdx.x;
    const int bid = blockIdx.x;
    const int rank = (bid < 148) ? bid : ((bid < 296) ? (443 - bid) : bid);
    const int item = c_order[rank >> 3];
    const int b = rank & 7;

    int qt, j0, j1, split;
    bool is_split;
    if (item < 32) {
        qt = 16 + (item >> 1);
        split = item & 1;
        int jm = qt >> 1;
        int h = (jm + 1) >> 1;
        if (split == 0) { j0 = 0; j1 = h - 1; }
        else            { j0 = h; j1 = jm; }
        is_split = true;
    } else {
        qt = item - 32;
        split = 0;
        j0 = 0; j1 = qt >> 1;
        is_split = false;
    }
    const int jmaskg = qt >> 1;
    const int qrow0 = qt * QT;
    const __half* kbase = kb + (size_t)b * TT * HH;

    const int w = tid >> 5, lane = tid & 31, gid = lane >> 2, t4 = lane & 3;

    const uint32_t aQ_lane = sQa +
        (uint32_t)((16 * w + (lane & 15)) * QS2 + ((lane >> 4) << 3)) * 2;
    const uint32_t bK_lane = sKa +
        (uint32_t)((((lane & 7) + ((lane & 16) ? 8 : 0)) * KS2) + ((lane & 8) ? 8 : 0)) * 2;
    const uint32_t vV_lane = sKa +
        (uint32_t)((((lane & 7) + ((lane & 8) ? 8 : 0)) * KS2) + ((lane & 16) ? 8 : 0)) * 2;

    // load Q tile (plain copy; 1/32 scale folded into exp via C1)
    #pragma unroll
    for (int i = tid; i < QT * (HH / 8); i += 128) {
        int r = i >> 3, c = i & 7;
        *(uint4*)&sQ[r * QS2 + c * 8] =
            *(const uint4*)(kbase + (size_t)(qrow0 + r) * HH + c * 8);
    }

    float m0 = -1e30f, m1 = -1e30f, l0 = 0.f, l1 = 0.f;
    const int rg0 = qrow0 + 16 * w + gid;
    const int rg1 = rg0 + 8;

    float o[8][4];
    #pragma unroll
    for (int i = 0; i < 8; i++)
        #pragma unroll
        for (int l = 0; l < 4; l++) o[i][l] = 0.f;

    for (int j = j0; j <= j1; j++) {
        __syncthreads();
        #pragma unroll
        for (int i = tid; i < KT * (HH / 8); i += 128) {
            int r = i >> 3, c = i & 7;
            *(uint4*)&sK[r * KS2 + c * 8] =
                *(const uint4*)(kbase + (size_t)(j * KT + r) * HH + c * 8);
        }
        __syncthreads();

        // ---- S = Q K^T ----
        float s[16][4];
        #pragma unroll
        for (int nt = 0; nt < 16; nt++)
            #pragma unroll
            for (int l = 0; l < 4; l++) s[nt][l] = 0.f;

        #pragma unroll
        for (int c = 0; c < 4; c++) {
            uint32_t a[4];
            ldsm4(a[0], a[1], a[2], a[3], aQ_lane + c * 32);
            #pragma unroll
            for (int a8 = 0; a8 < 8; a8++) {
                uint32_t b0, b1, b2, b3;
                ldsm4(b0, b1, b2, b3,
                      bK_lane + (uint32_t)(a8 * 16 * KS2) * 2 + c * 32);
                mma16(s[2 * a8],     a, b0, b1);
                mma16(s[2 * a8 + 1], a, b2, b3);
            }
        }

        // ---- causal mask (diagonal tile only) ----
        if (j == jmaskg) {
            #pragma unroll
            for (int nt = 0; nt < 16; nt++) {
                int kc = j * KT + 8 * nt + 2 * t4;
                if (kc     > rg0) s[nt][0] = -1e30f;
                if (kc + 1 > rg0) s[nt][1] = -1e30f;
                if (kc     > rg1) s[nt][2] = -1e30f;
                if (kc + 1 > rg1) s[nt][3] = -1e30f;
            }
        }

        // ---- online softmax ----
        float mx0 = -1e30f, mx1 = -1e30f;
        #pragma unroll
        for (int nt = 0; nt < 16; nt++) {
            mx0 = fmaxf(mx0, fmaxf(s[nt][0], s[nt][1]));
            mx1 = fmaxf(mx1, fmaxf(s[nt][2], s[nt][3]));
        }
        mx0 = fmaxf(mx0, __shfl_xor_sync(0xffffffffu, mx0, 1));
        mx0 = fmaxf(mx0, __shfl_xor_sync(0xffffffffu, mx0, 2));
        mx1 = fmaxf(mx1, __shfl_xor_sync(0xffffffffu, mx1, 1));
        mx1 = fmaxf(mx1, __shfl_xor_sync(0xffffffffu, mx1, 2));

        float mn0 = fmaxf(m0, mx0), mn1 = fmaxf(m1, mx1);
        float al0 = ex2f((m0 - mn0) * C1), al1 = ex2f((m1 - mn1) * C1);
        m0 = mn0; m1 = mn1;
        float mc0 = mn0 * C1, mc1 = mn1 * C1;

        // P = 2^(s*C1 - mc) via ex2.f16x2; lands directly in PV A-frag layout
        uint32_t pa[8][4];
        #pragma unroll
        for (int nt = 0; nt < 16; nt++) {
            float t0 = s[nt][0] * C1 - mc0;
            float t1 = s[nt][1] * C1 - mc0;
            float t2 = s[nt][2] * C1 - mc1;
            float t3 = s[nt][3] * C1 - mc1;
            uint32_t u01 = h2ex2(packh2(t0, t1));
            uint32_t u23 = h2ex2(packh2(t2, t3));
            pa[nt >> 1][(nt & 1) * 2]     = u01;
            pa[nt >> 1][(nt & 1) * 2 + 1] = u23;
        }

        #pragma unroll
        for (int nt = 0; nt < 8; nt++) {
            o[nt][0] *= al0; o[nt][1] *= al0; o[nt][2] *= al1; o[nt][3] *= al1;
        }

        // ---- O += P V ; l-partials via mma against ones-B ----
        float lacc[4] = { 0.f, 0.f, 0.f, 0.f };
        #pragma unroll
        for (int kk = 0; kk < 8; kk++) {
            mma16(lacc, pa[kk], ONESH2, ONESH2);
            #pragma unroll
            for (int a2 = 0; a2 < 4; a2++) {
                uint32_t v0, v1, v2, v3;
                ldsm4t(v0, v1, v2, v3,
                       vV_lane + (uint32_t)(kk * 16 * KS2) * 2 + a2 * 32);
                mma16(o[2 * a2],     pa[kk], v0, v1);
                mma16(o[2 * a2 + 1], pa[kk], v2, v3);
            }
        }
        l0 = l0 * al0 + lacc[0];
        l1 = l1 * al1 + lacc[2];
    }

    const int lr0 = 16 * w + gid, lr1 = lr0 + 8;

    if (!is_split) {
        float il0 = 1.f / l0, il1 = 1.f / l1;
        float* ob = out + (size_t)b * TT * HH;
        #pragma unroll
        for (int nt = 0; nt < 8; nt++) {
            int c = 8 * nt + 2 * t4;
            float2 r0v = { o[nt][0] * il0, o[nt][1] * il0 };
            float2 r1v = { o[nt][2] * il1, o[nt][3] * il1 };
            *(float2*)(ob + (size_t)rg0 * HH + c) = r0v;
            *(float2*)(ob + (size_t)rg1 * HH + c) = r1v;
        }
    } else if (split == 0) {
        const int pair = b * 16 + (qt - 16);
        float* po = part + (size_t)pair * (QT * HH);
        #pragma unroll
        for (int nt = 0; nt < 8; nt++) {
            int c = 8 * nt + 2 * t4;
            float2 r0v = { o[nt][0], o[nt][1] };
            float2 r1v = { o[nt][2], o[nt][3] };
            *(float2*)(po + lr0 * HH + c) = r0v;
            *(float2*)(po + lr1 * HH + c) = r1v;
        }
        if (t4 == 0) {
            stats[pair * 128 + lr0 * 2]     = m0;
            stats[pair * 128 + lr0 * 2 + 1] = l0;
            stats[pair * 128 + lr1 * 2]     = m1;
            stats[pair * 128 + lr1 * 2 + 1] = l1;
        }
        __syncthreads();
        if (tid == 0) {
            __threadfence();
            atomicExch(&flags[pair], 1);
        }
    } else {
        const int pair = b * 16 + (qt - 16);
        if (tid == 0) {
            while (atomicAdd(&flags[pair], 0) == 0) __nanosleep(32);
        }
        __syncthreads();
        __threadfence();

        const float* po = part + (size_t)pair * (QT * HH);
        float2 st0 = __ldcg((const float2*)&stats[pair * 128 + lr0 * 2]);
        float2 st1 = __ldcg((const float2*)&stats[pair * 128 + lr1 * 2]);

        float mm0 = fmaxf(st0.x, m0);
        float a00 = ex2f((st0.x - mm0) * C1), a01 = ex2f((m0 - mm0) * C1);
        float iv0 = 1.f / (a00 * st0.y + a01 * l0);
        float mm1 = fmaxf(st1.x, m1);
        float a10 = ex2f((st1.x - mm1) * C1), a11 = ex2f((m1 - mm1) * C1);
        float iv1 = 1.f / (a10 * st1.y + a11 * l1);

        float* ob = out + (size_t)b * TT * HH;
        #pragma unroll
        for (int nt = 0; nt < 8; nt++) {
            int c = 8 * nt + 2 * t4;
            float2 ua = __ldcg((const float2*)(po + lr0 * HH + c));
            float2 ub = __ldcg((const float2*)(po + lr1 * HH + c));
            float2 r0v = { (a00 * ua.x + a01 * o[nt][0]) * iv0,
                           (a00 * ua.y + a01 * o[nt][1]) * iv0 };
            float2 r1v = { (a10 * ub.x + a11 * o[nt][2]) * iv1,
                           (a10 * ub.y + a11 * o[nt][3]) * iv1 };
            *(float2*)(ob + (size_t)rg0 * HH + c) = r0v;
            *(float2*)(ob + (size_t)rg1 * HH + c) = r1v;
        }
        __syncthreads();
        if (tid == 0) flags[pair] = 0;
    }
}

// ---------------------------------------------------------------------------
// launch
// ---------------------------------------------------------------------------
extern "C" void kernel_launch(void* const* d_in, const int* in_sizes, int n_in,
                              void* d_out, int out_size)
{
    const float* x = (const float*)d_in[0];   // [B, T, C]
    const float* W = (const float*)d_in[1];   // [H, C]
    float* out = (float*)d_out;               // [B, T, H]

    __half *kbuf = nullptr, *wt = nullptr;
    float *part = nullptr, *stats = nullptr;
    int* flags = nullptr;
    cudaGetSymbolAddress((void**)&kbuf, g_kbuf);
    cudaGetSymbolAddress((void**)&wt, g_wt);
    cudaGetSymbolAddress((void**)&part, g_part);
    cudaGetSymbolAddress((void**)&stats, g_stats);
    cudaGetSymbolAddress((void**)&flags, g_flags);

    cudaFuncSetAttribute(proj_kernel, cudaFuncAttributeMaxDynamicSharedMemorySize,
                         PROJ_SMEM_BYTES);
    cudaFuncSetAttribute(attn_kernel, cudaFuncAttributeMaxDynamicSharedMemorySize,
                         ATTN_SMEM_BYTES);

    wconv_kernel<<<128, 128>>>(W, wt);

    proj_kernel<<<(BB * TT) / PROJ_M, 256, PROJ_SMEM_BYTES>>>(x, wt, kbuf);

    attn_kernel<<<384, 128, ATTN_SMEM_BYTES>>>(kbuf, out, part, stats, flags);
}